// round 1
// baseline (speedup 1.0000x reference)
#include <cuda_runtime.h>
#include <cuda_bf16.h>
#include <math.h>

// Problem constants
#define BATCH 2
#define SEQ   2048
#define EMB   1024
#define NHEAD 16
#define HDIM  64
#define E3    3072   // 3*EMB

// Scratch (allocation-free rule: __device__ globals)
__device__ float g_qkv[(size_t)BATCH * SEQ * E3];          // 50 MB
__device__ float g_ctx[(size_t)BATCH * SEQ * EMB];         // 16 MB
__device__ float g_attn[(size_t)BATCH * NHEAD * SEQ * SEQ]; // 512 MB fallback if attn not in d_out

// ---------------------------------------------------------------------------
// Generic SGEMM: C[M,N] = A[M,K] @ B[K,N] + bias[N]
// 128x128 block, BK=8, 256 threads, 8x8 per-thread microtile.
// Requires M%128==0, N%128==0, K%8==0 (true for all uses here).
// ---------------------------------------------------------------------------
__global__ __launch_bounds__(256) void sgemm_bias_kernel(
    const float* __restrict__ A, const float* __restrict__ B,
    const float* __restrict__ bias, float* __restrict__ C,
    int M, int N, int K)
{
    __shared__ float As[8][128];
    __shared__ float Bs[8][128];

    const int tid  = threadIdx.x;
    const int brow = blockIdx.y * 128;
    const int bcol = blockIdx.x * 128;
    const int ty = tid / 16;      // 0..15
    const int tx = tid % 16;      // 0..15

    // A-tile load map: 128 rows x 8 cols = 256 float4 -> 1 per thread
    const int arow = tid >> 1;           // 0..127
    const int acol = (tid & 1) * 4;      // 0 or 4
    // B-tile load map: 8 rows x 128 cols = 256 float4 -> 1 per thread
    const int blrow = tid >> 5;          // 0..7
    const int blcol = (tid & 31) * 4;    // 0..124

    const float* Ag = A + (size_t)brow * K;
    const float* Bg = B + bcol;

    float acc[8][8];
    #pragma unroll
    for (int i = 0; i < 8; i++)
        #pragma unroll
        for (int j = 0; j < 8; j++) acc[i][j] = 0.f;

    for (int k0 = 0; k0 < K; k0 += 8) {
        float4 a = *(const float4*)(Ag + (size_t)arow * K + k0 + acol);
        As[acol + 0][arow] = a.x;
        As[acol + 1][arow] = a.y;
        As[acol + 2][arow] = a.z;
        As[acol + 3][arow] = a.w;
        float4 b = *(const float4*)(Bg + (size_t)(k0 + blrow) * N + blcol);
        *(float4*)&Bs[blrow][blcol] = b;
        __syncthreads();

        #pragma unroll
        for (int k = 0; k < 8; k++) {
            float ra[8], rb[8];
            #pragma unroll
            for (int i = 0; i < 8; i++) ra[i] = As[k][ty * 8 + i];
            #pragma unroll
            for (int j = 0; j < 8; j++) rb[j] = Bs[k][tx * 8 + j];
            #pragma unroll
            for (int i = 0; i < 8; i++)
                #pragma unroll
                for (int j = 0; j < 8; j++)
                    acc[i][j] = fmaf(ra[i], rb[j], acc[i][j]);
        }
        __syncthreads();
    }

    #pragma unroll
    for (int i = 0; i < 8; i++) {
        const int r = brow + ty * 8 + i;
        float* Crow = C + (size_t)r * N + bcol + tx * 8;
        #pragma unroll
        for (int jj = 0; jj < 8; jj += 4) {
            float4 o;
            o.x = acc[i][jj + 0] + bias[bcol + tx * 8 + jj + 0];
            o.y = acc[i][jj + 1] + bias[bcol + tx * 8 + jj + 1];
            o.z = acc[i][jj + 2] + bias[bcol + tx * 8 + jj + 2];
            o.w = acc[i][jj + 3] + bias[bcol + tx * 8 + jj + 3];
            *(float4*)(Crow + jj) = o;
        }
    }
}

// ---------------------------------------------------------------------------
// Scores: logits[b,h,i,j] = (Q[i,:].K[j,:]) / 8 + slope(h) * (j - i)
// Q,K strided inside qkv [B,S,H,3D]: q at h*192+d, k at h*192+64+d.
// Block: 128x128 output tile, K-dim = 64 in 4 chunks of 16. 256 threads, 8x8.
// ---------------------------------------------------------------------------
__global__ __launch_bounds__(256) void scores_kernel(
    const float* __restrict__ qkv, float* __restrict__ attn)
{
    __shared__ float Qs[16][128];
    __shared__ float Ks[16][128];

    const int bh = blockIdx.z;
    const int b  = bh / NHEAD;
    const int h  = bh % NHEAD;
    const int i0 = blockIdx.y * 128;
    const int j0 = blockIdx.x * 128;

    const float* Qg = qkv + (size_t)b * SEQ * E3 + h * 192;
    const float* Kg = qkv + (size_t)b * SEQ * E3 + h * 192 + 64;

    const int tid = threadIdx.x;
    const int ty = tid / 16, tx = tid % 16;

    float acc[8][8];
    #pragma unroll
    for (int i = 0; i < 8; i++)
        #pragma unroll
        for (int j = 0; j < 8; j++) acc[i][j] = 0.f;

    for (int d0 = 0; d0 < HDIM; d0 += 16) {
        // 128 rows x 16 floats = 512 float4 -> 2 per thread, stored transposed
        #pragma unroll
        for (int t = 0; t < 2; t++) {
            const int idx = tid + 256 * t;
            const int row = idx >> 2;          // 0..127
            const int col = (idx & 3) * 4;     // 0..12
            float4 q = *(const float4*)(Qg + (size_t)(i0 + row) * E3 + d0 + col);
            Qs[col + 0][row] = q.x;
            Qs[col + 1][row] = q.y;
            Qs[col + 2][row] = q.z;
            Qs[col + 3][row] = q.w;
            float4 k = *(const float4*)(Kg + (size_t)(j0 + row) * E3 + d0 + col);
            Ks[col + 0][row] = k.x;
            Ks[col + 1][row] = k.y;
            Ks[col + 2][row] = k.z;
            Ks[col + 3][row] = k.w;
        }
        __syncthreads();

        #pragma unroll
        for (int d = 0; d < 16; d++) {
            float ra[8], rb[8];
            #pragma unroll
            for (int i = 0; i < 8; i++) ra[i] = Qs[d][ty * 8 + i];
            #pragma unroll
            for (int j = 0; j < 8; j++) rb[j] = Ks[d][tx * 8 + j];
            #pragma unroll
            for (int i = 0; i < 8; i++)
                #pragma unroll
                for (int j = 0; j < 8; j++)
                    acc[i][j] = fmaf(ra[i], rb[j], acc[i][j]);
        }
        __syncthreads();
    }

    const float slope = exp2f(-0.5f * (float)(h + 1));
    #pragma unroll
    for (int i = 0; i < 8; i++) {
        const int gi = i0 + ty * 8 + i;
        float* dst = attn + ((size_t)bh * SEQ + gi) * SEQ + j0 + tx * 8;
        #pragma unroll
        for (int jj = 0; jj < 8; jj += 4) {
            const int gj = j0 + tx * 8 + jj;
            float4 o;
            o.x = acc[i][jj + 0] * 0.125f + slope * (float)(gj + 0 - gi);
            o.y = acc[i][jj + 1] * 0.125f + slope * (float)(gj + 1 - gi);
            o.z = acc[i][jj + 2] * 0.125f + slope * (float)(gj + 2 - gi);
            o.w = acc[i][jj + 3] * 0.125f + slope * (float)(gj + 3 - gi);
            *(float4*)(dst + jj) = o;
        }
    }
}

// ---------------------------------------------------------------------------
// Row softmax over last dim (S=2048), in place. One block (256 thr) per row.
// ---------------------------------------------------------------------------
__global__ __launch_bounds__(256) void softmax_kernel(float* __restrict__ attn)
{
    float* p = attn + (size_t)blockIdx.x * SEQ;
    const int tid = threadIdx.x;

    float4 a = ((const float4*)p)[tid];
    float4 b = ((const float4*)p)[tid + 256];

    float m = fmaxf(fmaxf(fmaxf(a.x, a.y), fmaxf(a.z, a.w)),
                    fmaxf(fmaxf(b.x, b.y), fmaxf(b.z, b.w)));
    #pragma unroll
    for (int o = 16; o > 0; o >>= 1)
        m = fmaxf(m, __shfl_xor_sync(0xffffffffu, m, o));

    __shared__ float sm[8];
    __shared__ float ss[8];
    if ((tid & 31) == 0) sm[tid >> 5] = m;
    __syncthreads();
    m = sm[0];
    #pragma unroll
    for (int w = 1; w < 8; w++) m = fmaxf(m, sm[w]);

    a.x = expf(a.x - m); a.y = expf(a.y - m); a.z = expf(a.z - m); a.w = expf(a.w - m);
    b.x = expf(b.x - m); b.y = expf(b.y - m); b.z = expf(b.z - m); b.w = expf(b.w - m);

    float s = a.x + a.y + a.z + a.w + b.x + b.y + b.z + b.w;
    #pragma unroll
    for (int o = 16; o > 0; o >>= 1)
        s += __shfl_xor_sync(0xffffffffu, s, o);
    if ((tid & 31) == 0) ss[tid >> 5] = s;
    __syncthreads();
    s = ss[0];
    #pragma unroll
    for (int w = 1; w < 8; w++) s += ss[w];

    const float inv = 1.0f / s;
    a.x *= inv; a.y *= inv; a.z *= inv; a.w *= inv;
    b.x *= inv; b.y *= inv; b.z *= inv; b.w *= inv;
    ((float4*)p)[tid]       = a;
    ((float4*)p)[tid + 256] = b;
}

// ---------------------------------------------------------------------------
// AV: ctx[b,q,h,d] = sum_k attn[b,h,q,k] * v[b,k,h,d]
// Per block: 128 q-rows x 64 d-cols, K chunks of 16. 256 threads, 8x4 microtile.
// ---------------------------------------------------------------------------
__global__ __launch_bounds__(256) void av_kernel(
    const float* __restrict__ attn, const float* __restrict__ qkv,
    float* __restrict__ ctx)
{
    __shared__ float As[16][128];
    __shared__ float Vs[16][64];

    const int bh = blockIdx.y;
    const int b  = bh / NHEAD;
    const int h  = bh % NHEAD;
    const int i0 = blockIdx.x * 128;

    const float* Ag = attn + ((size_t)bh * SEQ + i0) * SEQ;
    const float* Vg = qkv + (size_t)b * SEQ * E3 + h * 192 + 128;

    const int tid = threadIdx.x;
    const int ty = tid / 16, tx = tid % 16;

    float acc[8][4];
    #pragma unroll
    for (int i = 0; i < 8; i++)
        #pragma unroll
        for (int j = 0; j < 4; j++) acc[i][j] = 0.f;

    const int vrow = tid >> 4;          // 0..15
    const int vcol = (tid & 15) * 4;    // 0..60

    for (int k0 = 0; k0 < SEQ; k0 += 16) {
        #pragma unroll
        for (int t = 0; t < 2; t++) {
            const int idx = tid + 256 * t;
            const int row = idx >> 2;
            const int col = (idx & 3) * 4;
            float4 a = *(const float4*)(Ag + (size_t)row * SEQ + k0 + col);
            As[col + 0][row] = a.x;
            As[col + 1][row] = a.y;
            As[col + 2][row] = a.z;
            As[col + 3][row] = a.w;
        }
        float4 v = *(const float4*)(Vg + (size_t)(k0 + vrow) * E3 + vcol);
        *(float4*)&Vs[vrow][vcol] = v;
        __syncthreads();

        #pragma unroll
        for (int k = 0; k < 16; k++) {
            float ra[8];
            #pragma unroll
            for (int i = 0; i < 8; i++) ra[i] = As[k][ty * 8 + i];
            float4 vv = *(const float4*)&Vs[k][tx * 4];
            const float rv[4] = {vv.x, vv.y, vv.z, vv.w};
            #pragma unroll
            for (int i = 0; i < 8; i++)
                #pragma unroll
                for (int j = 0; j < 4; j++)
                    acc[i][j] = fmaf(ra[i], rv[j], acc[i][j]);
        }
        __syncthreads();
    }

    #pragma unroll
    for (int i = 0; i < 8; i++) {
        const int q = i0 + ty * 8 + i;
        float4 o = {acc[i][0], acc[i][1], acc[i][2], acc[i][3]};
        *(float4*)&ctx[((size_t)(b * SEQ + q)) * EMB + h * HDIM + tx * 4] = o;
    }
}

// ---------------------------------------------------------------------------
extern "C" void kernel_launch(void* const* d_in, const int* in_sizes, int n_in,
                              void* d_out, int out_size)
{
    const float* x    = (const float*)d_in[0];  // [B,S,E]
    const float* Wqkv = (const float*)d_in[1];  // [E,3E]
    const float* bqkv = (const float*)d_in[2];  // [3E]
    const float* Wout = (const float*)d_in[3];  // [E,E]
    const float* bout = (const float*)d_in[4];  // [E]

    float* out = (float*)d_out;

    const long long OUT_ELEMS  = (long long)BATCH * SEQ * EMB;              // 4,194,304
    const long long ATTN_ELEMS = (long long)BATCH * NHEAD * SEQ * SEQ;      // 134,217,728

    float* qkv;  cudaGetSymbolAddress((void**)&qkv,  g_qkv);
    float* ctx;  cudaGetSymbolAddress((void**)&ctx,  g_ctx);
    float* attn;
    if ((long long)out_size >= OUT_ELEMS + ATTN_ELEMS) {
        attn = out + OUT_ELEMS;     // outputs are (out, attn) concatenated
    } else {
        cudaGetSymbolAddress((void**)&attn, g_attn);
    }

    const int M = BATCH * SEQ;  // 4096

    // 1) QKV projection: [4096,1024] @ [1024,3072] + bias
    {
        dim3 grid(E3 / 128, M / 128);
        sgemm_bias_kernel<<<grid, 256>>>(x, Wqkv, bqkv, qkv, M, E3, EMB);
    }
    // 2) Scores + ALiBi
    {
        dim3 grid(SEQ / 128, SEQ / 128, BATCH * NHEAD);
        scores_kernel<<<grid, 256>>>(qkv, attn);
    }
    // 3) Softmax over rows
    {
        softmax_kernel<<<BATCH * NHEAD * SEQ, 256>>>(attn);
    }
    // 4) AV
    {
        dim3 grid(SEQ / 128, BATCH * NHEAD);
        av_kernel<<<grid, 256>>>(attn, qkv, ctx);
    }
    // 5) Output projection: [4096,1024] @ [1024,1024] + bias
    {
        dim3 grid(EMB / 128, M / 128);
        sgemm_bias_kernel<<<grid, 256>>>(ctx, Wout, bout, out, M, EMB, EMB);
    }
}

// round 3
// speedup vs baseline: 1.3558x; 1.3558x over previous
#include <cuda_runtime.h>
#include <mma.h>
#include <cstdint>
#include <math.h>

using namespace nvcuda;

#define BATCH 2
#define SEQ   2048
#define EMB   1024
#define NHEAD 16
#define HDIM  64
#define E3    3072

// Scratch (__device__ globals per allocation rules)
__device__ float g_qkv [(size_t)BATCH * SEQ * E3];            // 50 MB
__device__ float g_ctx [(size_t)BATCH * SEQ * EMB];           // 16 MB
__device__ float g_attn[(size_t)BATCH * NHEAD * SEQ * SEQ];   // 512 MB fallback

typedef wmma::fragment<wmma::matrix_a, 16, 16, 8, wmma::precision::tf32, wmma::row_major> FragA;
typedef wmma::fragment<wmma::matrix_b, 16, 16, 8, wmma::precision::tf32, wmma::row_major> FragBR;
typedef wmma::fragment<wmma::matrix_b, 16, 16, 8, wmma::precision::tf32, wmma::col_major> FragBC;
typedef wmma::fragment<wmma::accumulator, 16, 16, 8, float> FragC;

template<class F>
__device__ __forceinline__ void to_tf32(F& f) {
    #pragma unroll
    for (int i = 0; i < f.num_elements; i++) f.x[i] = wmma::__float_to_tf32(f.x[i]);
}

// ---------------------------------------------------------------------------
// GEMM + bias: C[M,N] = A[M,K] @ B[K,N] + bias[N]
// BM=128, BN=128, BK=32, 256 threads (8 warps: 4 row x 2 col),
// warp tile 32x64 = 2x4 wmma tiles (16x16x8 tf32).
// ---------------------------------------------------------------------------
#define GSM (128 * 132 * 4)   // 67584 B: C staging; mainloop uses a prefix

__global__ __launch_bounds__(256) void gemm_bias_w(
    const float* __restrict__ A, const float* __restrict__ B,
    const float* __restrict__ bias, float* __restrict__ C, int K, int N)
{
    extern __shared__ float sm[];
    float* As = sm;                 // [128][36]
    float* Bs = sm + 128 * 36;      // [32][132]
    float* Cs = sm;                 // [128][132] (reused after mainloop)

    const int m0 = blockIdx.y * 128, n0 = blockIdx.x * 128;
    const int tid = threadIdx.x;
    const int w = tid >> 5;
    const int wr = w >> 1, wc = w & 1;

    FragC acc[2][4];
    #pragma unroll
    for (int i = 0; i < 2; i++)
        #pragma unroll
        for (int j = 0; j < 4; j++) wmma::fill_fragment(acc[i][j], 0.f);

    for (int k0 = 0; k0 < K; k0 += 32) {
        // As: 128x32
        #pragma unroll
        for (int t = 0; t < 4; t++) {
            int idx = tid + t * 256;
            int r = idx >> 3, c = (idx & 7) * 4;
            *(float4*)&As[r * 36 + c] = *(const float4*)&A[(size_t)(m0 + r) * K + k0 + c];
        }
        // Bs: 32x128
        #pragma unroll
        for (int t = 0; t < 4; t++) {
            int idx = tid + t * 256;
            int r = idx >> 5, c = (idx & 31) * 4;
            *(float4*)&Bs[r * 132 + c] = *(const float4*)&B[(size_t)(k0 + r) * N + n0 + c];
        }
        __syncthreads();

        #pragma unroll
        for (int kk = 0; kk < 32; kk += 8) {
            FragA a[2];
            FragBR b[4];
            #pragma unroll
            for (int i = 0; i < 2; i++) {
                wmma::load_matrix_sync(a[i], &As[(wr * 32 + i * 16) * 36 + kk], 36);
                to_tf32(a[i]);
            }
            #pragma unroll
            for (int j = 0; j < 4; j++) {
                wmma::load_matrix_sync(b[j], &Bs[kk * 132 + wc * 64 + j * 16], 132);
                to_tf32(b[j]);
            }
            #pragma unroll
            for (int i = 0; i < 2; i++)
                #pragma unroll
                for (int j = 0; j < 4; j++)
                    wmma::mma_sync(acc[i][j], a[i], b[j], acc[i][j]);
        }
        __syncthreads();
    }

    // Epilogue via smem staging
    #pragma unroll
    for (int i = 0; i < 2; i++)
        #pragma unroll
        for (int j = 0; j < 4; j++)
            wmma::store_matrix_sync(&Cs[(wr * 32 + i * 16) * 132 + wc * 64 + j * 16],
                                    acc[i][j], 132, wmma::mem_row_major);
    __syncthreads();
    #pragma unroll
    for (int t = 0; t < 16; t++) {
        int idx = tid + t * 256;
        int r = idx >> 5, c = (idx & 31) * 4;
        float4 v = *(float4*)&Cs[r * 132 + c];
        const float* bp = bias + n0 + c;
        v.x += bp[0]; v.y += bp[1]; v.z += bp[2]; v.w += bp[3];
        *(float4*)&C[(size_t)(m0 + r) * N + n0 + c] = v;
    }
}

// ---------------------------------------------------------------------------
// Scores: attn[bh,i,j] = (Q_i . K_j)/8 + slope(h)*(j-i).  grid(16,16,32)
// BK=32, 2 k-chunks (D=64). B is K^T -> col_major frags from row-major K tile.
// ---------------------------------------------------------------------------
__global__ __launch_bounds__(256) void scores_w(
    const float* __restrict__ qkv, float* __restrict__ attn)
{
    extern __shared__ float sm[];
    float* Qs = sm;              // [128][36]
    float* Ks = sm + 128 * 36;   // [128][36]
    float* Cs = sm;              // [128][132]

    const int bh = blockIdx.z, b = bh >> 4, h = bh & 15;
    const int i0 = blockIdx.y * 128, j0 = blockIdx.x * 128;
    const float* Qg = qkv + (size_t)b * SEQ * E3 + h * 192;
    const float* Kg = qkv + (size_t)b * SEQ * E3 + h * 192 + 64;

    const int tid = threadIdx.x;
    const int w = tid >> 5;
    const int wr = w >> 1, wc = w & 1;

    FragC acc[2][4];
    #pragma unroll
    for (int i = 0; i < 2; i++)
        #pragma unroll
        for (int j = 0; j < 4; j++) wmma::fill_fragment(acc[i][j], 0.f);

    #pragma unroll
    for (int k0 = 0; k0 < HDIM; k0 += 32) {
        #pragma unroll
        for (int t = 0; t < 4; t++) {
            int idx = tid + t * 256;
            int r = idx >> 3, c = (idx & 7) * 4;
            *(float4*)&Qs[r * 36 + c] = *(const float4*)&Qg[(size_t)(i0 + r) * E3 + k0 + c];
            *(float4*)&Ks[r * 36 + c] = *(const float4*)&Kg[(size_t)(j0 + r) * E3 + k0 + c];
        }
        __syncthreads();

        #pragma unroll
        for (int kk = 0; kk < 32; kk += 8) {
            FragA a[2];
            FragBC bfr[4];
            #pragma unroll
            for (int i = 0; i < 2; i++) {
                wmma::load_matrix_sync(a[i], &Qs[(wr * 32 + i * 16) * 36 + kk], 36);
                to_tf32(a[i]);
            }
            #pragma unroll
            for (int j = 0; j < 4; j++) {
                wmma::load_matrix_sync(bfr[j], &Ks[(wc * 64 + j * 16) * 36 + kk], 36);
                to_tf32(bfr[j]);
            }
            #pragma unroll
            for (int i = 0; i < 2; i++)
                #pragma unroll
                for (int j = 0; j < 4; j++)
                    wmma::mma_sync(acc[i][j], a[i], bfr[j], acc[i][j]);
        }
        __syncthreads();
    }

    #pragma unroll
    for (int i = 0; i < 2; i++)
        #pragma unroll
        for (int j = 0; j < 4; j++)
            wmma::store_matrix_sync(&Cs[(wr * 32 + i * 16) * 132 + wc * 64 + j * 16],
                                    acc[i][j], 132, wmma::mem_row_major);
    __syncthreads();

    const float slope = exp2f(-0.5f * (float)(h + 1));
    #pragma unroll
    for (int t = 0; t < 16; t++) {
        int idx = tid + t * 256;
        int r = idx >> 5, c = (idx & 31) * 4;
        const int gi = i0 + r, gj = j0 + c;
        float4 v = *(float4*)&Cs[r * 132 + c];
        v.x = v.x * 0.125f + slope * (float)(gj + 0 - gi);
        v.y = v.y * 0.125f + slope * (float)(gj + 1 - gi);
        v.z = v.z * 0.125f + slope * (float)(gj + 2 - gi);
        v.w = v.w * 0.125f + slope * (float)(gj + 3 - gi);
        *(float4*)&attn[((size_t)bh * SEQ + gi) * SEQ + gj] = v;
    }
}

// ---------------------------------------------------------------------------
// AV: ctx[b,q,h*64+d] = sum_k attn[bh,q,k] * V[k,d].  grid(16, 32)
// BM=128, BN=64, BK=32; warp tile 32x32 = 2x2 frags. V used row-major in place.
// ---------------------------------------------------------------------------
#define AVSM ((128 * 36 + 32 * 68) * 4)

__global__ __launch_bounds__(256) void av_w(
    const float* __restrict__ attn, const float* __restrict__ qkv,
    float* __restrict__ ctx)
{
    extern __shared__ float sm[];
    float* As = sm;              // [128][36]
    float* Vs = sm + 128 * 36;   // [32][68]

    const int bh = blockIdx.y, b = bh >> 4, h = bh & 15;
    const int i0 = blockIdx.x * 128;
    const float* Ag = attn + ((size_t)bh * SEQ + i0) * SEQ;
    const float* Vg = qkv + (size_t)b * SEQ * E3 + h * 192 + 128;

    const int tid = threadIdx.x;
    const int w = tid >> 5;
    const int wr = w >> 1, wc = w & 1;

    FragC acc[2][2];
    #pragma unroll
    for (int i = 0; i < 2; i++)
        #pragma unroll
        for (int j = 0; j < 2; j++) wmma::fill_fragment(acc[i][j], 0.f);

    for (int k0 = 0; k0 < SEQ; k0 += 32) {
        #pragma unroll
        for (int t = 0; t < 4; t++) {
            int idx = tid + t * 256;
            int r = idx >> 3, c = (idx & 7) * 4;
            *(float4*)&As[r * 36 + c] = *(const float4*)&Ag[(size_t)r * SEQ + k0 + c];
        }
        #pragma unroll
        for (int t = 0; t < 2; t++) {
            int idx = tid + t * 256;
            int r = idx >> 4, c = (idx & 15) * 4;
            *(float4*)&Vs[r * 68 + c] = *(const float4*)&Vg[(size_t)(k0 + r) * E3 + c];
        }
        __syncthreads();

        #pragma unroll
        for (int kk = 0; kk < 32; kk += 8) {
            FragA a[2];
            FragBR bfr[2];
            #pragma unroll
            for (int i = 0; i < 2; i++) {
                wmma::load_matrix_sync(a[i], &As[(wr * 32 + i * 16) * 36 + kk], 36);
                to_tf32(a[i]);
            }
            #pragma unroll
            for (int j = 0; j < 2; j++) {
                wmma::load_matrix_sync(bfr[j], &Vs[kk * 68 + wc * 32 + j * 16], 68);
                to_tf32(bfr[j]);
            }
            #pragma unroll
            for (int i = 0; i < 2; i++)
                #pragma unroll
                for (int j = 0; j < 2; j++)
                    wmma::mma_sync(acc[i][j], a[i], bfr[j], acc[i][j]);
        }
        __syncthreads();
    }

    // Direct fragment store to ctx (row-major, ld = EMB)
    #pragma unroll
    for (int i = 0; i < 2; i++) {
        const int q = i0 + wr * 32 + i * 16;
        #pragma unroll
        for (int j = 0; j < 2; j++)
            wmma::store_matrix_sync(
                &ctx[((size_t)(b * SEQ + q)) * EMB + h * HDIM + wc * 32 + j * 16],
                acc[i][j], EMB, wmma::mem_row_major);
    }
}

// ---------------------------------------------------------------------------
// Row softmax over last dim (S=2048), in place. One block (256 thr) per row.
// ---------------------------------------------------------------------------
__global__ __launch_bounds__(256) void softmax_kernel(float* __restrict__ attn)
{
    float* p = attn + (size_t)blockIdx.x * SEQ;
    const int tid = threadIdx.x;
    float4 a = ((const float4*)p)[tid];
    float4 b = ((const float4*)p)[tid + 256];

    float m = fmaxf(fmaxf(fmaxf(a.x, a.y), fmaxf(a.z, a.w)),
                    fmaxf(fmaxf(b.x, b.y), fmaxf(b.z, b.w)));
    #pragma unroll
    for (int o = 16; o > 0; o >>= 1)
        m = fmaxf(m, __shfl_xor_sync(0xffffffffu, m, o));

    __shared__ float sm_[8], ss[8];
    if ((tid & 31) == 0) sm_[tid >> 5] = m;
    __syncthreads();
    m = sm_[0];
    #pragma unroll
    for (int w = 1; w < 8; w++) m = fmaxf(m, sm_[w]);

    a.x = expf(a.x - m); a.y = expf(a.y - m); a.z = expf(a.z - m); a.w = expf(a.w - m);
    b.x = expf(b.x - m); b.y = expf(b.y - m); b.z = expf(b.z - m); b.w = expf(b.w - m);

    float s = a.x + a.y + a.z + a.w + b.x + b.y + b.z + b.w;
    #pragma unroll
    for (int o = 16; o > 0; o >>= 1)
        s += __shfl_xor_sync(0xffffffffu, s, o);
    if ((tid & 31) == 0) ss[tid >> 5] = s;
    __syncthreads();
    s = ss[0];
    #pragma unroll
    for (int w = 1; w < 8; w++) s += ss[w];

    const float inv = 1.0f / s;
    a.x *= inv; a.y *= inv; a.z *= inv; a.w *= inv;
    b.x *= inv; b.y *= inv; b.z *= inv; b.w *= inv;
    ((float4*)p)[tid]       = a;
    ((float4*)p)[tid + 256] = b;
}

// ---------------------------------------------------------------------------
extern "C" void kernel_launch(void* const* d_in, const int* in_sizes, int n_in,
                              void* d_out, int out_size)
{
    const float* x    = (const float*)d_in[0];
    const float* Wqkv = (const float*)d_in[1];
    const float* bqkv = (const float*)d_in[2];
    const float* Wout = (const float*)d_in[3];
    const float* bout = (const float*)d_in[4];
    float* out = (float*)d_out;

    const long long OUT_ELEMS  = (long long)BATCH * SEQ * EMB;
    const long long ATTN_ELEMS = (long long)BATCH * NHEAD * SEQ * SEQ;

    float *qkv, *ctx, *attn;
    cudaGetSymbolAddress((void**)&qkv, g_qkv);
    cudaGetSymbolAddress((void**)&ctx, g_ctx);
    if ((long long)out_size >= OUT_ELEMS + ATTN_ELEMS) {
        attn = out + OUT_ELEMS;
    } else {
        cudaGetSymbolAddress((void**)&attn, g_attn);
    }

    cudaFuncSetAttribute(gemm_bias_w, cudaFuncAttributeMaxDynamicSharedMemorySize, GSM);
    cudaFuncSetAttribute(scores_w,    cudaFuncAttributeMaxDynamicSharedMemorySize, GSM);
    cudaFuncSetAttribute(av_w,        cudaFuncAttributeMaxDynamicSharedMemorySize, AVSM);

    const int M = BATCH * SEQ;  // 4096

    // 1) QKV projection: [4096,1024] @ [1024,3072] + bias
    gemm_bias_w<<<dim3(E3 / 128, M / 128), 256, GSM>>>(x, Wqkv, bqkv, qkv, EMB, E3);

    // 2) Scores + ALiBi
    scores_w<<<dim3(SEQ / 128, SEQ / 128, BATCH * NHEAD), 256, GSM>>>(qkv, attn);

    // 3) Softmax
    softmax_kernel<<<BATCH * NHEAD * SEQ, 256>>>(attn);

    // 4) AV
    av_w<<<dim3(SEQ / 128, BATCH * NHEAD), 256, AVSM>>>(attn, qkv, ctx);

    // 5) Output projection
    gemm_bias_w<<<dim3(EMB / 128, M / 128), 256, GSM>>>(ctx, Wout, bout, out, EMB, EMB);
}